// round 6
// baseline (speedup 1.0000x reference)
#include <cuda_runtime.h>
#include <math.h>

#define B 32
#define N 2048
#define BN (B*N)

// chamfer config
#define CTHREADS 128
#define QPT 8
#define QPB (CTHREADS*QPT)       // 1024 queries per block
#define QCHUNKS 2                // N / QPB
#define DCHUNKS 8
#define DTILE (N/DCHUNKS)        // 256
#define BLKS_PER_DB (QCHUNKS*DCHUNKS)   // 16 blocks feed one (dir,b)

// prep config
#define PBLOCKS 256              // B * 8 segments
#define PTHREADS 256

typedef unsigned long long u64;

// ---------------- scratch (device globals; zero at module load) -------------
__device__ float g_Px[BN], g_Py[BN], g_Pnq[BN], g_Pnd[BN];
__device__ float g_Tx[BN], g_Ty[BN], g_Tnq[BN], g_Tnd[BN];
__device__ unsigned g_minbits[2*BN];     // per-(dir,b,q) min d2 bits
__device__ float g_ppart[PBLOCKS*5];     // {point,mask,struct,cntP,cntT} per prep block
__device__ float g_chsum[2*B];           // per-(dir,b) sqrt-sums
__device__ int   g_dbticket[2*B];        // per-(dir,b) arrival counters
__device__ int   g_fticket;              // combine ticket

// ---------------- packed f32x2 helpers --------------------------------------
__device__ __forceinline__ u64 pack2(float lo, float hi) {
    u64 r; asm("mov.b64 %0,{%1,%2};" : "=l"(r) : "f"(lo), "f"(hi)); return r;
}
__device__ __forceinline__ u64 fma2(u64 a, u64 b, u64 c) {
    u64 d; asm("fma.rn.f32x2 %0,%1,%2,%3;" : "=l"(d) : "l"(a), "l"(b), "l"(c)); return d;
}
__device__ __forceinline__ void unpack2(u64 v, float& lo, float& hi) {
    asm("mov.b64 {%0,%1},%2;" : "=f"(lo), "=f"(hi) : "l"(v));
}

// ---------------- prep: pure map (no atomics) + partials ---------------------
__global__ void __launch_bounds__(PTHREADS) sk_prep_kernel(
        const float* __restrict__ pred,
        const float* __restrict__ target,
        const float* __restrict__ smask) {
    int bx = blockIdx.x;
    int b = bx >> 3, seg = bx & 7;
    int n = seg * PTHREADS + threadIdx.x;
    int idx = b * N + n;
    int lane = threadIdx.x & 31, wid = threadIdx.x >> 5;
    __shared__ float red[40];   // 8 warps x 5

    float p0 = pred[idx*3+0],  p1 = pred[idx*3+1],  p2 = pred[idx*3+2];
    float t0 = target[idx*3+0], t1 = target[idx*3+1], t2 = target[idx*3+2];
    bool tv = (t2 == 1.0f);
    bool pv = (p2 == 1.0f);

    float s_point = 0.f, s_mask = 0.f, s_struct = 0.f;
    if (tv) {
        float d0 = p0 - t0, d1 = p1 - t1;
        s_point = d0*d0 + d1*d1;
        float m0 = smask[idx*2+0], m1 = smask[idx*2+1];
        float sm = fminf(fmaxf(m0 + m1, 0.f), 1.f);
        s_mask = sm;
        float e0 = d0 * sm, e1 = d1 * sm;
        s_struct = e0*e0 + e1*e1;
    }

    float px = pv ? p0 : 0.f, py = pv ? p1 : 0.f;
    float tx = tv ? t0 : 0.f, ty = tv ? t1 : 0.f;
    float np = px*px + py*py, nt = tx*tx + ty*ty;
    g_Px[idx] = px;  g_Py[idx] = py;
    g_Pnq[idx] = pv ? np : -1.f;
    g_Pnd[idx] = pv ? np : 3.0e38f;
    g_Tx[idx] = tx;  g_Ty[idx] = ty;
    g_Tnq[idx] = tv ? nt : -1.f;
    g_Tnd[idx] = tv ? nt : 3.0e38f;

    // fresh min slots each replay
    g_minbits[(0*B + b)*N + n] = 0x7F7FFFFFu;
    g_minbits[(1*B + b)*N + n] = 0x7F7FFFFFu;

    float cp = pv ? 1.f : 0.f, ct = tv ? 1.f : 0.f;
    #pragma unroll
    for (int o = 16; o; o >>= 1) {
        s_point  += __shfl_xor_sync(0xffffffffu, s_point,  o);
        s_mask   += __shfl_xor_sync(0xffffffffu, s_mask,   o);
        s_struct += __shfl_xor_sync(0xffffffffu, s_struct, o);
        cp       += __shfl_xor_sync(0xffffffffu, cp,       o);
        ct       += __shfl_xor_sync(0xffffffffu, ct,       o);
    }
    if (lane == 0) {
        red[wid] = s_point; red[8+wid] = s_mask; red[16+wid] = s_struct;
        red[24+wid] = cp; red[32+wid] = ct;
    }
    __syncthreads();
    if (threadIdx.x == 0) {
        float a=0.f,c=0.f,d=0.f,e=0.f,f=0.f;
        #pragma unroll
        for (int w = 0; w < 8; w++) {
            a += red[w]; c += red[8+w]; d += red[16+w];
            e += red[24+w]; f += red[32+w];
        }
        g_ppart[bx*5+0]=a; g_ppart[bx*5+1]=c; g_ppart[bx*5+2]=d;
        g_ppart[bx*5+3]=e; g_ppart[bx*5+4]=f;
    }
}

// ---------------- chamfer + fused reductions ---------------------------------
__global__ void __launch_bounds__(CTHREADS) sk_chamfer_kernel(float* __restrict__ out) {
    int qchunk = blockIdx.x, b = blockIdx.y;
    int dir = blockIdx.z >> 3, dchunk = blockIdx.z & 7;
    int db = dir * B + b;
    int tid = threadIdx.x;

    const float *Qx, *Qy, *Qnq, *Dx, *Dy, *Dnd;
    if (dir == 0) {
        Qx = g_Px + b*N; Qy = g_Py + b*N; Qnq = g_Pnq + b*N;
        Dx = g_Tx + b*N; Dy = g_Ty + b*N; Dnd = g_Tnd + b*N;
    } else {
        Qx = g_Tx + b*N; Qy = g_Ty + b*N; Qnq = g_Tnq + b*N;
        Dx = g_Px + b*N; Dy = g_Py + b*N; Dnd = g_Pnd + b*N;
    }

    __shared__ u64 s2[3*DTILE];   // 6 KB duplicated {-2x}, {-2y}, {n}

    int dstart = dchunk * DTILE;
    #pragma unroll
    for (int it = 0; it < DTILE / CTHREADS; it++) {
        int j = it * CTHREADS + tid;
        int g = dstart + j;
        float x = -2.0f * Dx[g], y = -2.0f * Dy[g], n2 = Dnd[g];
        s2[j]           = pack2(x, x);
        s2[DTILE + j]   = pack2(y, y);
        s2[2*DTILE + j] = pack2(n2, n2);
    }

    int qbase = qchunk * QPB;
    u64 px2[QPT/2], py2[QPT/2];
    float pn[QPT], mm[QPT];
    #pragma unroll
    for (int k = 0; k < QPT/2; k++) {
        int q0 = qbase + (2*k)   * CTHREADS + tid;
        int q1 = qbase + (2*k+1) * CTHREADS + tid;
        px2[k] = pack2(Qx[q0], Qx[q1]);
        py2[k] = pack2(Qy[q0], Qy[q1]);
        pn[2*k] = Qnq[q0]; pn[2*k+1] = Qnq[q1];
        mm[2*k] = 3.0e38f; mm[2*k+1] = 3.0e38f;
    }
    __syncthreads();

    #pragma unroll 4
    for (int j = 0; j < DTILE; j++) {
        u64 tx = s2[j], ty = s2[DTILE + j], tn = s2[2*DTILE + j];
        #pragma unroll
        for (int k = 0; k < QPT/2; k++) {
            u64 d = fma2(px2[k], tx, fma2(py2[k], ty, tn));
            float lo, hi; unpack2(d, lo, hi);
            mm[2*k]   = fminf(mm[2*k],   lo);
            mm[2*k+1] = fminf(mm[2*k+1], hi);
        }
    }

    unsigned* minb = g_minbits + db * N;
    #pragma unroll
    for (int i = 0; i < QPT; i++) {
        int q = qbase + i * CTHREADS + tid;
        float v = fmaxf(pn[i] + mm[i], 1e-12f);   // clamp keeps bits monotone
        atomicMin(&minb[q], __float_as_uint(v));
    }

    // ---- ticket 1: last block of this (dir,b) does the sqrt-sum -------------
    __shared__ int s_tkt;
    __shared__ float wred[4];
    if (tid == 0) {
        __threadfence();
        s_tkt = atomicAdd(&g_dbticket[db], 1);
    }
    __syncthreads();
    if (s_tkt != BLKS_PER_DB - 1) return;
    if (tid == 0) g_dbticket[db] = 0;      // reset for next replay
    __threadfence();

    float s = 0.f;
    #pragma unroll
    for (int it = 0; it < N / CTHREADS; it++) {
        int q = it * CTHREADS + tid;
        unsigned mb = g_minbits[db * N + q];
        if (Qnq[q] >= 0.f) s += sqrtf(__uint_as_float(mb));
    }
    #pragma unroll
    for (int o = 16; o; o >>= 1) s += __shfl_xor_sync(0xffffffffu, s, o);
    if ((tid & 31) == 0) wred[tid >> 5] = s;
    __syncthreads();

    __shared__ int s_ft;
    if (tid == 0) {
        g_chsum[db] = wred[0] + wred[1] + wred[2] + wred[3];
        __threadfence();
        s_ft = atomicAdd(&g_fticket, 1);
    }
    __syncthreads();
    if (s_ft != 2*B - 1) return;
    if (tid == 0) g_fticket = 0;
    __threadfence();

    // ---- ticket 2 winner: scalar combine ------------------------------------
    __shared__ float sred[12];   // 4 warps x 3
    __shared__ float sb[2*B];    // per-b cntP / cntT
    volatile float* vch = g_chsum;

    float sp = 0.f, smk = 0.f, sst = 0.f;
    #pragma unroll
    for (int it = 0; it < PBLOCKS / CTHREADS; it++) {
        int blk = it * CTHREADS + tid;
        sp  += g_ppart[blk*5+0];
        smk += g_ppart[blk*5+1];
        sst += g_ppart[blk*5+2];
    }
    #pragma unroll
    for (int o = 16; o; o >>= 1) {
        sp  += __shfl_xor_sync(0xffffffffu, sp,  o);
        smk += __shfl_xor_sync(0xffffffffu, smk, o);
        sst += __shfl_xor_sync(0xffffffffu, sst, o);
    }
    if ((tid & 31) == 0) { int w = tid >> 5; sred[w]=sp; sred[4+w]=smk; sred[8+w]=sst; }

    if (tid < 2*B) {                         // per-b counts
        int bb = tid & 31, which = (tid < B) ? 3 : 4;
        float c = 0.f;
        #pragma unroll
        for (int seg = 0; seg < 8; seg++) c += g_ppart[(bb*8+seg)*5 + which];
        sb[tid] = c;
    }
    __syncthreads();

    float ch = 0.f;
    if (tid < B) {
        float cp = sb[tid], ct = sb[B + tid];
        float mp = vch[tid]     / fmaxf(cp, 1.f);   // dir0: queries = preds
        float mt = vch[B + tid] / fmaxf(ct, 1.f);   // dir1: queries = targets
        ch = (cp > 0.f && ct > 0.f) ? 0.5f * (mp + mt) : 0.f;
    }
    #pragma unroll
    for (int o = 16; o; o >>= 1) ch += __shfl_xor_sync(0xffffffffu, ch, o);

    if (tid == 0) {
        float a = 0.f, c = 0.f, d = 0.f;
        #pragma unroll
        for (int w = 0; w < 4; w++) { a += sred[w]; c += sred[4+w]; d += sred[8+w]; }
        float lc = ch / (float)B;
        float lp = a / (float)(B * N * 2);
        float ls = (c > 0.f) ? d / (float)(B * N * 2) : 0.f;
        out[0] = lp + 5.0f * lc + 2.0f * ls;
        out[1] = lp;
        out[2] = 0.f;
        out[3] = lc;
    }
}

extern "C" void kernel_launch(void* const* d_in, const int* in_sizes, int n_in,
                              void* d_out, int out_size) {
    const float* pred   = (const float*)d_in[0];
    const float* target = (const float*)d_in[1];
    const float* smask  = (const float*)d_in[2];
    float* out = (float*)d_out;

    sk_prep_kernel<<<PBLOCKS, PTHREADS>>>(pred, target, smask);
    dim3 cgrid(QCHUNKS, B, 2 * DCHUNKS);
    sk_chamfer_kernel<<<cgrid, CTHREADS>>>(out);
}